// round 1
// baseline (speedup 1.0000x reference)
#include <cuda_runtime.h>
#include <math.h>

#define Bb   4
#define Ls   1024
#define Hh   768
#define NHh  12
#define NEe  30
#define Mm   6
#define Pp   600
#define EMBe 768
#define BSs  16
#define NCc  97
#define K2H  1536           // 2*H
#define QQ   12288          // EMB*BS
#define BP   (Bb*Pp)        // 2400

// ---------------- scratch (static device globals; no allocation) ----------------
__device__ float g_e_emb[Bb*NEe*Hh];        // [B,NE,H]
__device__ float g_e_att[Bb*NEe*NHh*Ls];    // [B,NE,NH,L]
__device__ float g_ht  [Bb*Pp*Ls];          // [B,P,L]
__device__ float g_rs  [Bb*Pp*Hh];          // [B,P,H]
__device__ float g_hs  [BP*EMBe];           // [B*P,EMB]
__device__ float g_ts  [BP*EMBe];           // [B*P,EMB]
__device__ float g_Wc  [NCc*QQ];            // [NC, EMB*BS]  = cls_W @ proj_W

// ---------------- kernel 1: entity pooling -------------------------------------
// e_emb[b,e,h] = logsumexp_m( mask? seq[b,idx,h] : -1e30 )
// e_att[b,e,nh,l] = sum_m mask*att[b,nh,idx,l] / max(sum mask,1)
__global__ void pool_kernel(const float* __restrict__ seq,
                            const float* __restrict__ att,
                            const float* __restrict__ mmask,
                            const int*   __restrict__ midx)
{
    int be = blockIdx.x;               // 0..B*NE-1
    int b = be / NEe;
    __shared__ int   idx[Mm];
    __shared__ float msk[Mm];
    if (threadIdx.x < Mm) {
        idx[threadIdx.x] = midx[be*Mm + threadIdx.x];
        msk[threadIdx.x] = mmask[be*Mm + threadIdx.x];
    }
    __syncthreads();
    float cnt = 0.f;
    #pragma unroll
    for (int m = 0; m < Mm; m++) cnt += msk[m];
    cnt = fmaxf(cnt, 1.0f);
    float invc = 1.0f / cnt;

    // logsumexp over mentions
    for (int h = threadIdx.x; h < Hh; h += blockDim.x) {
        float v[Mm]; float mx = -1e30f;
        #pragma unroll
        for (int m = 0; m < Mm; m++) {
            float x = seq[((long)b*Ls + idx[m])*Hh + h];
            x = (msk[m] > 0.f) ? x : -1e30f;
            v[m] = x; mx = fmaxf(mx, x);
        }
        float s = 0.f;
        #pragma unroll
        for (int m = 0; m < Mm; m++) s += expf(v[m] - mx);
        g_e_emb[(long)be*Hh + h] = mx + logf(s);
    }
    // attention mean over mentions
    for (int t = threadIdx.x; t < NHh*Ls; t += blockDim.x) {
        int nh = t >> 10, l = t & (Ls-1);
        float s = 0.f;
        #pragma unroll
        for (int m = 0; m < Mm; m++)
            s += att[(((long)b*NHh + nh)*Ls + idx[m])*Ls + l] * msk[m];
        g_e_att[((long)be*NHh + nh)*Ls + l] = s * invc;
    }
}

// ---------------- kernel 2: pairwise attention mix + normalize ------------------
__global__ void htatt_kernel(const int* __restrict__ hts)
{
    int bp = blockIdx.x;               // 0..B*P-1
    int b = bp / Pp;
    int he = hts[bp*2 + 0];
    int te = hts[bp*2 + 1];
    const float* ha = &g_e_att[((long)(b*NEe + he))*NHh*Ls];
    const float* ta = &g_e_att[((long)(b*NEe + te))*NHh*Ls];
    __shared__ float sv[Ls];
    __shared__ float red[256];
    float lsum = 0.f;
    for (int l = threadIdx.x; l < Ls; l += blockDim.x) {
        float s = 0.f;
        #pragma unroll
        for (int nh = 0; nh < NHh; nh++)
            s += ha[nh*Ls + l] * ta[nh*Ls + l];
        s *= (1.0f / NHh);
        sv[l] = s; lsum += s;
    }
    red[threadIdx.x] = lsum;
    for (int o = 128; o > 0; o >>= 1) {
        __syncthreads();
        if (threadIdx.x < o) red[threadIdx.x] += red[threadIdx.x + o];
    }
    __syncthreads();
    float inv = 1.0f / (red[0] + 1e-30f);
    for (int l = threadIdx.x; l < Ls; l += blockDim.x)
        g_ht[(long)bp*Ls + l] = sv[l] * inv;
}

// ---------------- generic batched NN GEMM: C = A @ B ---------------------------
// A [M,K] row-major, B [K,N] row-major, C [M,N] row-major. N%64==0, K%16==0.
__global__ void gemm_nn(const float* __restrict__ A, const float* __restrict__ Bm,
                        float* __restrict__ C,
                        int M, int N, int K, long sA, long sB, long sC)
{
    __shared__ float As[16][65];
    __shared__ float Bs[16][65];
    int bz = blockIdx.z;
    const float* Ab = A + (long)bz*sA;
    const float* Bp = Bm + (long)bz*sB;
    float*       Cb = C + (long)bz*sC;
    int m0 = blockIdx.x*64, n0 = blockIdx.y*64;
    int tid = threadIdx.x;
    int tm = tid & 15, tn = tid >> 4;
    float acc[4][4] = {};
    for (int k0 = 0; k0 < K; k0 += 16) {
        #pragma unroll
        for (int i = 0; i < 4; i++) {
            int idx = tid + i*256;
            int m = idx >> 4, k = idx & 15;
            float v = 0.f;
            if (m0 + m < M) v = Ab[(long)(m0 + m)*K + k0 + k];
            As[k][m] = v;
        }
        #pragma unroll
        for (int i = 0; i < 4; i++) {
            int idx = tid + i*256;
            int k = idx >> 6, n = idx & 63;
            Bs[k][n] = Bp[(long)(k0 + k)*N + n0 + n];
        }
        __syncthreads();
        #pragma unroll
        for (int kk = 0; kk < 16; kk++) {
            float a[4], bb[4];
            #pragma unroll
            for (int i = 0; i < 4; i++) a[i]  = As[kk][tm + 16*i];
            #pragma unroll
            for (int j = 0; j < 4; j++) bb[j] = Bs[kk][tn + 16*j];
            #pragma unroll
            for (int i = 0; i < 4; i++)
                #pragma unroll
                for (int j = 0; j < 4; j++)
                    acc[i][j] += a[i]*bb[j];
        }
        __syncthreads();
    }
    #pragma unroll
    for (int i = 0; i < 4; i++) {
        int m = m0 + tm + 16*i;
        if (m >= M) continue;
        #pragma unroll
        for (int j = 0; j < 4; j++) {
            int n = n0 + tn + 16*j;
            if (n < N) Cb[(long)m*N + n] = acc[i][j];
        }
    }
}

// ---------------- kernel 4: extractor GEMM (gathered A, B^T, tanh) -------------
// out[b,p,e] = tanh( bias[e] + sum_k X[b,p,k] * W[e,k] )
// X[:, :768] = e_emb[b, hts[b,p,side]], X[:, 768:] = rs[b,p]
__global__ void extract_gemm(const float* __restrict__ headW, const float* __restrict__ headb,
                             const float* __restrict__ tailW, const float* __restrict__ tailb,
                             const int*   __restrict__ hts)
{
    int z = blockIdx.z;
    int b = z >> 1, side = z & 1;
    const float* W    = side ? tailW : headW;
    const float* bias = side ? tailb : headb;
    float*       out  = side ? g_ts  : g_hs;
    __shared__ float As[16][65];
    __shared__ float Bs[16][65];
    __shared__ int   ent_s[64];
    int m0 = blockIdx.x*64, n0 = blockIdx.y*64;
    int tid = threadIdx.x;
    if (tid < 64) {
        int p = m0 + tid;
        ent_s[tid] = (p < Pp) ? hts[((b*Pp + p)*2) + side] : 0;
    }
    __syncthreads();
    int tm = tid & 15, tn = tid >> 4;
    float acc[4][4] = {};
    for (int k0 = 0; k0 < K2H; k0 += 16) {
        #pragma unroll
        for (int i = 0; i < 4; i++) {
            int idx = tid + i*256;
            int m = idx >> 4, k = idx & 15;
            int p = m0 + m;
            int kk = k0 + k;
            float v = 0.f;
            if (p < Pp) {
                if (kk < Hh) v = g_e_emb[((long)(b*NEe + ent_s[m]))*Hh + kk];
                else         v = g_rs[((long)(b*Pp + p))*Hh + (kk - Hh)];
            }
            As[k][m] = v;
        }
        #pragma unroll
        for (int i = 0; i < 4; i++) {
            int idx = tid + i*256;
            int e = idx >> 4, k = idx & 15;      // B^T load: contiguous in k
            Bs[k][e] = W[(long)(n0 + e)*K2H + k0 + k];
        }
        __syncthreads();
        #pragma unroll
        for (int kk = 0; kk < 16; kk++) {
            float a[4], bb[4];
            #pragma unroll
            for (int i = 0; i < 4; i++) a[i]  = As[kk][tm + 16*i];
            #pragma unroll
            for (int j = 0; j < 4; j++) bb[j] = Bs[kk][tn + 16*j];
            #pragma unroll
            for (int i = 0; i < 4; i++)
                #pragma unroll
                for (int j = 0; j < 4; j++)
                    acc[i][j] += a[i]*bb[j];
        }
        __syncthreads();
    }
    #pragma unroll
    for (int i = 0; i < 4; i++) {
        int m = m0 + tm + 16*i;
        if (m >= Pp) continue;
        #pragma unroll
        for (int j = 0; j < 4; j++) {
            int e = n0 + tn + 16*j;
            out[((long)(b*Pp + m))*EMBe + e] = tanhf(acc[i][j] + bias[e]);
        }
    }
}

// ---------------- kernel 6: block-bilinear classifier --------------------------
// out[m,c] = cls_b[c] + sum_{k,i,j} hs[m,16k+i]*ts[m,16k+j]*Wc[c,256k+16i+j]
// Tile: 64 pairs x 32 classes; A row regenerated on the fly (never materialized).
__global__ void bilinear_kernel(const float* __restrict__ clsb, float* __restrict__ out)
{
    __shared__ float hs_s[64][17];
    __shared__ float ts_s[64][17];
    __shared__ float Wc_s[256][33];
    int m0 = blockIdx.x*64;
    int c0 = blockIdx.y*32;
    int tid = threadIdx.x;
    int tm = tid & 15, tc = tid >> 4;
    float acc[4][2] = {};
    for (int kb = 0; kb < EMBe/16; kb++) {
        #pragma unroll
        for (int i = 0; i < 4; i++) {
            int idx = tid + i*256;
            int m = idx >> 4, k = idx & 15;
            float hv = 0.f, tv = 0.f;
            if (m0 + m < BP) {
                hv = g_hs[(long)(m0 + m)*EMBe + kb*16 + k];
                tv = g_ts[(long)(m0 + m)*EMBe + kb*16 + k];
            }
            hs_s[m][k] = hv; ts_s[m][k] = tv;
        }
        #pragma unroll
        for (int i = 0; i < 32; i++) {
            int idx = tid + i*256;        // 0..8191
            int c = idx >> 8, q = idx & 255;
            float w = 0.f;
            if (c0 + c < NCc) w = g_Wc[(long)(c0 + c)*QQ + kb*256 + q];
            Wc_s[q][c] = w;
        }
        __syncthreads();
        #pragma unroll 1
        for (int i = 0; i < 16; i++) {
            float a[4];
            #pragma unroll
            for (int im = 0; im < 4; im++) a[im] = hs_s[tm + 16*im][i];
            #pragma unroll
            for (int j = 0; j < 16; j++) {
                float w0 = Wc_s[i*16 + j][tc];
                float w1 = Wc_s[i*16 + j][tc + 16];
                #pragma unroll
                for (int im = 0; im < 4; im++) {
                    float pv = a[im] * ts_s[tm + 16*im][j];
                    acc[im][0] += pv * w0;
                    acc[im][1] += pv * w1;
                }
            }
        }
        __syncthreads();
    }
    #pragma unroll
    for (int im = 0; im < 4; im++) {
        int m = m0 + tm + 16*im;
        if (m >= BP) continue;
        #pragma unroll
        for (int jc = 0; jc < 2; jc++) {
            int c = c0 + tc + 16*jc;
            if (c < NCc) out[(long)m*NCc + c] = acc[im][jc] + clsb[c];
        }
    }
}

// ---------------- launch --------------------------------------------------------
extern "C" void kernel_launch(void* const* d_in, const int* in_sizes, int n_in,
                              void* d_out, int out_size)
{
    const float* seq   = (const float*)d_in[0];
    const float* att   = (const float*)d_in[1];
    const float* headW = (const float*)d_in[2];
    const float* headb = (const float*)d_in[3];
    const float* tailW = (const float*)d_in[4];
    const float* tailb = (const float*)d_in[5];
    const float* projW = (const float*)d_in[6];
    const float* clsW  = (const float*)d_in[7];
    const float* clsb  = (const float*)d_in[8];
    const float* mmask = (const float*)d_in[9];
    const int*   midx  = (const int*)d_in[10];
    const int*   hts   = (const int*)d_in[11];
    float* out = (float*)d_out;

    float *p_ht, *p_rs, *p_Wc;
    cudaGetSymbolAddress((void**)&p_ht, g_ht);
    cudaGetSymbolAddress((void**)&p_rs, g_rs);
    cudaGetSymbolAddress((void**)&p_Wc, g_Wc);

    // Wc = cls_W @ proj_W   [97,768] @ [768,12288] (independent; launch first)
    {
        dim3 g((NCc + 63)/64, QQ/64, 1);
        gemm_nn<<<g, 256>>>(clsW, projW, p_Wc, NCc, QQ, Hh, 0, 0, 0);
    }
    pool_kernel<<<Bb*NEe, 256>>>(seq, att, mmask, midx);
    htatt_kernel<<<Bb*Pp, 256>>>(hts);
    // rs[b] = ht[b] (600x1024) @ seq[b] (1024x768)
    {
        dim3 g((Pp + 63)/64, Hh/64, Bb);
        gemm_nn<<<g, 256>>>(p_ht, seq, p_rs, Pp, Hh, Ls,
                            (long)Pp*Ls, (long)Ls*Hh, (long)Pp*Hh);
    }
    // hs / ts extractors
    {
        dim3 g((Pp + 63)/64, EMBe/64, Bb*2);
        extract_gemm<<<g, 256>>>(headW, headb, tailW, tailb, hts);
    }
    // block-bilinear classifier
    {
        dim3 g((BP + 63)/64, (NCc + 31)/32, 1);
        bilinear_kernel<<<g, 256>>>(clsb, out);
    }
}